// round 15
// baseline (speedup 1.0000x reference)
#include <cuda_runtime.h>
#include <cuda_fp16.h>

#define NN 1000
#define DD 128
#define NEGV (-1e9f)
typedef unsigned long long u64;
typedef unsigned int u32;

// fp16 copy of embeddings [b][row][128 halves], written by phase 0
__device__ __align__(16) __half2 g_e16[(size_t)256 * NN * 64];

// ---- smem word offsets ----
#define O_A     0        // 16384: four 16384B chunk buffers (256 rows x 80B each)
#define O_AT    16384    // 4128: s_atT fp16 [8][1032]
#define O_C     20512    // 4096: compat fp16 [8][1024] / s_p f32 / ebar / s_lg
#define O_QT    24608    // 544: qtT fp16 [8][136]
#define O_GT16  25152    // 64: gt fp16 [128]
#define O_S0    25216    // 128: mean / heads
#define O_S1    25344    // 128: q / gl
#define O_S2    25472    // 128: ef / gt
#define O_S3    25600    // 128: el
#define O_RED   25728    // 32
#define SM_WORDS 25760   // 103040 bytes

static __device__ __forceinline__ float tanh_fast(float x) {
    float y; asm("tanh.approx.f32 %0, %1;" : "=f"(y) : "f"(x)); return y;
}
static __device__ __forceinline__ u32 f2h2(float a, float b) {
    __half2 h = __floats2half2_rn(a, b); return *(u32*)&h;
}
static __device__ __forceinline__ void cp16(void* dst, const void* src) {
    u32 sa = (u32)__cvta_generic_to_shared(dst);
    asm volatile("cp.async.cg.shared.global [%0], [%1], 16;" :: "r"(sa), "l"(src));
}
static __device__ __forceinline__ void mma16816(float* c, u32 a0, u32 a1, u32 a2, u32 a3,
                                                u32 b0, u32 b1) {
    asm volatile("mma.sync.aligned.m16n8k16.row.col.f32.f16.f16.f32 "
        "{%0,%1,%2,%3},{%4,%5,%6,%7},{%8,%9},{%0,%1,%2,%3};"
        : "+f"(c[0]), "+f"(c[1]), "+f"(c[2]), "+f"(c[3])
        : "r"(a0), "r"(a1), "r"(a2), "r"(a3), "r"(b0), "r"(b1));
}
static __device__ __forceinline__ void ldsm4(u32 addr, u32& a0, u32& a1, u32& a2, u32& a3) {
    asm volatile("ldmatrix.sync.aligned.m8n8.x4.shared.b16 {%0,%1,%2,%3},[%4];"
        : "=r"(a0), "=r"(a1), "=r"(a2), "=r"(a3) : "r"(addr));
}
static __device__ __forceinline__ void ldsm4t(u32 addr, u32& a0, u32& a1, u32& a2, u32& a3) {
    asm volatile("ldmatrix.sync.aligned.m8n8.x4.trans.shared.b16 {%0,%1,%2,%3},[%4];"
        : "=r"(a0), "=r"(a1), "=r"(a2), "=r"(a3) : "r"(addr));
}
// pipeline wait for chunk ch of 16, 4 groups max in flight
static __device__ __forceinline__ void pipe_wait(int ch) {
    if (ch <= 12)      asm volatile("cp.async.wait_group 3;" ::: "memory");
    else if (ch == 13) asm volatile("cp.async.wait_group 2;" ::: "memory");
    else if (ch == 14) asm volatile("cp.async.wait_group 1;" ::: "memory");
    else               asm volatile("cp.async.wait_group 0;" ::: "memory");
}

__global__ __launch_bounds__(512, 2) void attn_v12(
    const float* __restrict__ emb, const float* __restrict__ Wn,
    const float* __restrict__ Wf, const float* __restrict__ Ws,
    const float* __restrict__ Wo, const int* __restrict__ fidx,
    const int* __restrict__ lidx, const int* __restrict__ mask,
    float* __restrict__ out)
{
    extern __shared__ float sm[];
    __half* smh = (__half*)sm;
    const int b = blockIdx.x, t = threadIdx.x;
    const int lane = t & 31, warp = t >> 5;
    const float* embB = emb + (size_t)b * NN * DD;
    const int* mkB = mask + (size_t)b * NN;
    __half2* e16B = g_e16 + (size_t)b * (NN * 64);
    const u32 sbase = (u32)__cvta_generic_to_shared(sm);

    // chunk ch (0..15): R = ch>>2 (256-row quarter), C = ch&3 (32-dim quarter)
    auto stage = [&](int ch) {
        int R = (ch >> 2) & 3, C = ch & 3;
        char* dstb = (char*)sm + (ch & 3) * 16384;
        const uint4* src = (const uint4*)e16B + C * 4;
        #pragma unroll
        for (int k = 0; k < 2; k++) {
            int i = (k << 9) + t;          // 0..1023
            int rl = i >> 2, seg = i & 3;  // 256 rows x 4 16B-granules
            int gr = R * 256 + rl; if (gr > NN - 1) gr = NN - 1;
            cp16(dstb + rl * 80 + seg * 16, src + (size_t)gr * 16 + seg);
        }
        asm volatile("cp.async.commit_group;" ::: "memory");
    };

    // ---- Phase 0: mean partials + fp16 conversion, MLP=8 ----
    {
        int c = t & 31, g = t >> 5;
        const float4* E4 = (const float4*)embB + c;
        uint2* O = (uint2*)e16B + c;
        float sx = 0, sy = 0, sz = 0, sw = 0;
        int k = 0;
        for (; k < 56; k += 8) {
            float4 v[8];
            #pragma unroll
            for (int j = 0; j < 8; j++) v[j] = E4[(size_t)(g + ((k + j) << 4)) * 32];
            #pragma unroll
            for (int j = 0; j < 8; j++) {
                uint2 h; h.x = f2h2(v[j].x, v[j].y); h.y = f2h2(v[j].z, v[j].w);
                O[(size_t)(g + ((k + j) << 4)) * 32] = h;
                sx += v[j].x; sy += v[j].y; sz += v[j].z; sw += v[j].w;
            }
        }
        for (; k < 63; k++) {
            int r = g + (k << 4);
            if (r < NN) {
                float4 v = E4[(size_t)r * 32];
                uint2 h; h.x = f2h2(v.x, v.y); h.y = f2h2(v.z, v.w);
                O[(size_t)r * 32] = h;
                sx += v.x; sy += v.y; sz += v.z; sw += v.w;
            }
        }
        *(float4*)(sm + O_C + g * 128 + c * 4) = make_float4(sx, sy, sz, sw);
    }
    if (t < 128)      sm[O_S2 + t] = embB[(size_t)fidx[b] * DD + t];
    else if (t < 256) sm[O_S3 + t - 128] = embB[(size_t)lidx[b] * DD + (t - 128)];
    __syncthreads();
    stage(0); stage(1); stage(2);   // P1 chunks 0-2 fill under mean/q/qt
    if (t < 128) {
        float m = 0.f;
        #pragma unroll
        for (int g = 0; g < 16; g++) m += sm[O_C + g * 128 + t];
        sm[O_S0 + t] = m * (1.0f / NN);
    }
    __syncthreads();
    // q = mean@Wf + [ef;el]@Ws (split accumulators)
    if (t < 128) {
        float a0 = 0.f, a1 = 0.f;
        #pragma unroll 4
        for (int i = 0; i < DD; i += 2) {
            a0 += sm[O_S0 + i] * Wf[i * DD + t];
            a1 += sm[O_S0 + i + 1] * Wf[(i + 1) * DD + t];
        }
        #pragma unroll 4
        for (int i = 0; i < DD; i += 2) {
            a0 += sm[O_S2 + i] * Ws[i * DD + t];
            a1 += sm[O_S2 + i + 1] * Ws[(i + 1) * DD + t];
        }
        #pragma unroll 4
        for (int i = 0; i < DD; i += 2) {
            a0 += sm[O_S3 + i] * Ws[(DD + i) * DD + t];
            a1 += sm[O_S3 + i + 1] * Ws[(DD + i + 1) * DD + t];
        }
        sm[O_S1 + t] = a0 + a1;
    }
    __syncthreads();
    // qtT fp16 [head][dim], stride 136, scale folded
    if (t < 256) {
        int d = t >> 1, q4 = t & 1;
        #pragma unroll
        for (int kk = 0; kk < 4; kk++) {
            int h = q4 * 4 + kk;
            const float* w = Wn + d * 384 + h * 16;
            const float* qq = sm + O_S1 + h * 16;
            float acc = 0.f;
            #pragma unroll
            for (int j = 0; j < 16; j++) acc += w[j] * qq[j];
            smh[2 * O_QT + h * 136 + d] = __float2half(acc * 0.25f);
        }
    }
    __syncthreads();

    // ---- Phase 1: compat via mma, 4-deep pipeline, preloaded B-frags ----
    {
        float cf[4];
        const int g = lane >> 2, tc = lane & 3, hq = lane >> 2;
        u32 bq0[8], bq1[8];
        #pragma unroll
        for (int i = 0; i < 8; i++) {   // i = C*2+kl, dims 16i..16i+16
            bq0[i] = *(const u32*)(smh + 2 * O_QT + hq * 136 + i * 16 + 2 * tc);
            bq1[i] = *(const u32*)(smh + 2 * O_QT + hq * 136 + i * 16 + 2 * tc + 8);
        }
        for (int ch = 0; ch < 16; ch++) {
            int R = ch >> 2, C = ch & 3;
            if (ch + 3 < 16) stage(ch + 3);
            pipe_wait(ch);
            __syncthreads();
            if (C == 0) { cf[0] = cf[1] = cf[2] = cf[3] = 0.f; }
            const u32 bufb = sbase + (u32)((ch & 3) * 16384);
            #pragma unroll
            for (int kl = 0; kl < 2; kl++) {
                int bi = C * 2 + kl;
                u32 addr = bufb + (u32)((warp * 16 + (lane & 15)) * 80 + (lane >> 4) * 16 + kl * 32);
                u32 a0, a1, a2, a3;
                ldsm4(addr, a0, a1, a2, a3);
                mma16816(cf, a0, a1, a2, a3, bq0[bi], bq1[bi]);
            }
            if (C == 3) {
                __half* cp = smh + 2 * O_C;
                int r0 = R * 256 + warp * 16 + g, r1 = r0 + 8;
                if (r0 < NN) {
                    cp[(2 * tc) * 1024 + r0]     = __float2half(cf[0]);
                    cp[(2 * tc + 1) * 1024 + r0] = __float2half(cf[1]);
                }
                if (r1 < NN) {
                    cp[(2 * tc) * 1024 + r1]     = __float2half(cf[2]);
                    cp[(2 * tc + 1) * 1024 + r1] = __float2half(cf[3]);
                }
            }
            __syncthreads();
        }
    }
    stage(0); stage(1); stage(2);   // P2 chunks 0-2 fill under the softmax

    // ---- Phase 1b: per-head softmax (2 warps/head), mask applied here ----
    {
        int h = warp >> 1, seg = warp & 1;
        const __half* row = smh + 2 * O_C + h * 1024;
        float mx = -1e30f;
        for (int n = seg * 32 + lane; n < NN; n += 64) {
            float v = mkB[n] ? -1e30f : __half2float(row[n]);
            mx = fmaxf(mx, v);
        }
        #pragma unroll
        for (int o = 16; o > 0; o >>= 1) mx = fmaxf(mx, __shfl_xor_sync(~0u, mx, o));
        if (lane == 0) sm[O_RED + warp] = mx;
        __syncthreads();
        float hm = fmaxf(sm[O_RED + 2 * h], sm[O_RED + 2 * h + 1]);
        float sme = 0.f;
        for (int n = seg * 32 + lane; n < NN; n += 64) {
            float v = mkB[n] ? -1e30f : __half2float(row[n]);
            sme += __expf(v - hm);
        }
        #pragma unroll
        for (int o = 16; o > 0; o >>= 1) sme += __shfl_xor_sync(~0u, sme, o);
        if (lane == 0) sm[O_RED + 16 + warp] = sme;
        __syncthreads();
        float inv = 1.0f / (sm[O_RED + 16 + 2 * h] + sm[O_RED + 16 + 2 * h + 1]);
        __half* at = smh + 2 * O_AT + h * 1032;
        for (int n = seg * 32 + lane; n < NN; n += 64) {
            float v = mkB[n] ? -1e30f : __half2float(row[n]);
            at[n] = __float2half(__expf(v - hm) * inv);
        }
    }
    if (t < 128) {   // zero attn pad rows 1000..1031
        int h = t >> 4, i = 1000 + (t & 15) * 2;
        *(u32*)(smh + 2 * O_AT + h * 1032 + i) = 0;
    }
    __syncthreads();

    // ---- Phase 2: ebar via mma + ldmatrix.trans, 4-deep pipeline ----
    {
        int m = warp & 7, kh = warp >> 3;
        float cf[4] = {0.f, 0.f, 0.f, 0.f};
        int srow = (lane & 7) + ((lane >> 4) & 1) * 8;
        int doff = ((lane >> 3) & 1) * 16 + (m & 1) * 32;
        const __half* atp = smh + 2 * O_AT + (lane >> 2) * 1032 + 2 * (lane & 3);
        for (int ch = 0; ch < 16; ch++) {
            int R = ch >> 2, C = ch & 3;
            if (ch + 3 < 16) stage(ch + 3);
            pipe_wait(ch);
            __syncthreads();
            if ((m >> 1) == C) {
                const u32 bufb = sbase + (u32)((ch & 3) * 16384);
                #pragma unroll
                for (int kt = 0; kt < 8; kt++) {
                    int klocal = kh * 8 + kt;          // k-tile within 256-row chunk
                    int rb = R * 256 + klocal * 16;
                    u32 b0 = *(const u32*)(atp + rb);
                    u32 b1 = *(const u32*)(atp + rb + 8);
                    u32 addr = bufb + (u32)((klocal * 16 + srow) * 80 + doff);
                    u32 a0, a1, a2, a3;
                    ldsm4t(addr, a0, a1, a2, a3);
                    mma16816(cf, a0, a1, a2, a3, b0, b1);
                }
            }
            __syncthreads();
        }
        stage(0); stage(1); stage(2);   // P3 chunks 0-2 fill under the matvecs
        // store partial frags to s_p [kh*8+m][16][8] f32 at O_C
        int g = lane >> 2, tc = lane & 3;
        float* sp = sm + O_C;
        *(float2*)(sp + ((kh * 8 + m) * 16 + g) * 8 + 2 * tc)     = make_float2(cf[0], cf[1]);
        *(float2*)(sp + ((kh * 8 + m) * 16 + g + 8) * 8 + 2 * tc) = make_float2(cf[2], cf[3]);
    }
    __syncthreads();
    // ebar[h][d] at O_C+2048   (warp m covers dims [16m,16m+16))
    for (int i = t; i < 1024; i += 512) {
        int h = i >> 7, d = i & 127, m2 = d >> 4, g2 = d & 15;
        sm[O_C + 2048 + i] = sm[O_C + (m2 * 16 + g2) * 8 + h]
                           + sm[O_C + ((8 + m2) * 16 + g2) * 8 + h];
    }
    __syncthreads();

    // ---- Phase 2b: heads -> glimpse -> gtilde (+ gt16), split accumulators ----
    if (t < 128) {
        int h = t >> 4;
        const float* eb = sm + O_C + 2048 + h * 128;
        float a0 = 0.f, a1 = 0.f;
        #pragma unroll 4
        for (int d = 0; d < DD; d += 2) {
            a0 += eb[d] * Wn[d * 384 + 128 + t];
            a1 += eb[d + 1] * Wn[(d + 1) * 384 + 128 + t];
        }
        sm[O_S0 + t] = a0 + a1;
    }
    __syncthreads();
    if (t < 128) {
        float a0 = 0.f, a1 = 0.f;
        #pragma unroll 4
        for (int i = 0; i < DD; i += 2) {
            a0 += sm[O_S0 + i] * Wo[i * DD + t];
            a1 += sm[O_S0 + i + 1] * Wo[(i + 1) * DD + t];
        }
        sm[O_S1 + t] = a0 + a1;
    }
    __syncthreads();
    if (t < 128) {
        const float* w = Wn + t * 384 + 256;
        float a0 = 0.f, a1 = 0.f;
        #pragma unroll 4
        for (int j = 0; j < DD; j += 2) {
            a0 += w[j] * sm[O_S1 + j];
            a1 += w[j + 1] * sm[O_S1 + j + 1];
        }
        sm[O_S2 + t] = (a0 + a1) * 0.08838834764831845f;
    }
    __syncthreads();
    if (t < 64) ((u32*)(sm + O_GT16))[t] = f2h2(sm[O_S2 + 2 * t], sm[O_S2 + 2 * t + 1]);
    __syncthreads();

    // ---- Phase 3: logits via mma (gt in B col 0), 4-deep, preloaded B-frags ----
    float* s_lg = sm + O_C;
    float lmax = -1e30f;
    {
        float cf[4];
        const int g = lane >> 2;
        u32 bg0[8], bg1[8];
        #pragma unroll
        for (int i = 0; i < 8; i++) {
            if (lane < 4) {
                bg0[i] = *(const u32*)(smh + 2 * O_GT16 + i * 16 + 2 * lane);
                bg1[i] = *(const u32*)(smh + 2 * O_GT16 + i * 16 + 2 * lane + 8);
            } else { bg0[i] = 0; bg1[i] = 0; }
        }
        for (int ch = 0; ch < 16; ch++) {
            int R = ch >> 2, C = ch & 3;
            if (ch + 3 < 16) stage(ch + 3);
            pipe_wait(ch);
            __syncthreads();
            if (C == 0) { cf[0] = cf[1] = cf[2] = cf[3] = 0.f; }
            const u32 bufb = sbase + (u32)((ch & 3) * 16384);
            #pragma unroll
            for (int kl = 0; kl < 2; kl++) {
                int bi = C * 2 + kl;
                u32 addr = bufb + (u32)((warp * 16 + (lane & 15)) * 80 + (lane >> 4) * 16 + kl * 32);
                u32 a0, a1, a2, a3;
                ldsm4(addr, a0, a1, a2, a3);
                mma16816(cf, a0, a1, a2, a3, bg0[bi], bg1[bi]);
            }
            if (C == 3 && (lane & 3) == 0) {
                int r0 = R * 256 + warp * 16 + g, r1 = r0 + 8;
                if (r0 < NN) {
                    float v = tanh_fast(cf[0]) * 10.0f;
                    if (mkB[r0]) v = NEGV;
                    s_lg[r0] = v; lmax = fmaxf(lmax, v);
                }
                if (r1 < NN) {
                    float v = tanh_fast(cf[2]) * 10.0f;
                    if (mkB[r1]) v = NEGV;
                    s_lg[r1] = v; lmax = fmaxf(lmax, v);
                }
            }
            __syncthreads();
        }
    }
    // ---- log-softmax over 1000 ----
    #pragma unroll
    for (int o = 16; o > 0; o >>= 1) lmax = fmaxf(lmax, __shfl_xor_sync(~0u, lmax, o));
    if (lane == 0) sm[O_RED + warp] = lmax;
    __syncthreads();
    float bmax = sm[O_RED + 0];
    #pragma unroll
    for (int w = 1; w < 16; w++) bmax = fmaxf(bmax, sm[O_RED + w]);
    float ls = 0.f;
    for (int n = t; n < NN; n += 512) ls += __expf(s_lg[n] - bmax);
    #pragma unroll
    for (int o = 16; o > 0; o >>= 1) ls += __shfl_xor_sync(~0u, ls, o);
    if (lane == 0) sm[O_RED + 16 + warp] = ls;
    __syncthreads();
    float tot = sm[O_RED + 16];
    #pragma unroll
    for (int w = 1; w < 16; w++) tot += sm[O_RED + 16 + w];
    float logZ = bmax + logf(tot);
    float* outB = out + (size_t)b * NN;
    for (int n = t; n < NN; n += 512) outB[n] = s_lg[n] - logZ;
}

extern "C" void kernel_launch(void* const* d_in, const int* in_sizes, int n_in,
                              void* d_out, int out_size) {
    const float* emb = (const float*)d_in[0];
    const float* Wn  = (const float*)d_in[1];
    const float* Wf  = (const float*)d_in[2];
    const float* Ws  = (const float*)d_in[3];
    const float* Wo  = (const float*)d_in[4];
    const int* fidx  = (const int*)d_in[5];
    const int* lidx  = (const int*)d_in[6];
    const int* mask  = (const int*)d_in[7];
    float* out = (float*)d_out;
    cudaFuncSetAttribute(attn_v12, cudaFuncAttributeMaxDynamicSharedMemorySize, SM_WORDS * 4);
    attn_v12<<<256, 512, SM_WORDS * 4>>>(emb, Wn, Wf, Ws, Wo, fidx, lidx, mask, out);
}

// round 16
// speedup vs baseline: 1.1865x; 1.1865x over previous
#include <cuda_runtime.h>
#include <cuda_fp16.h>

#define NN 1000
#define DD 128
#define NEGV (-1e9f)
typedef unsigned long long u64;
typedef unsigned int u32;

// fp16 copy of embeddings [b][row][128 halves], written by phase 0
__device__ __align__(16) __half2 g_e16[(size_t)256 * NN * 64];

// ---- smem word offsets ----
#define O_A     0        // 17408: two 34816B chunk buffers (128 rows x 272B)
#define O_AT    17408    // 544: attn tile fp16 [8][136] (chunk-local)
#define O_P     17952    // 2048: partials (mean / compat / ebar-final / P3 logit)
#define O_LG    20000    // 1024: ebar[h][d] then s_lg[1000]
#define O_QT    21024    // 544: qtT fp16 [8][136]
#define O_GT16  21568    // 64: gt fp16 [128]
#define O_S0    21632    // mean / heads
#define O_S1    21760    // q / gl
#define O_S2    21888    // ef / gt
#define O_S3    22016    // el
#define O_MS    22144    // 32: m[8], s[8], f[8], inv[8]
#define O_RED   22176    // 32
#define SM_WORDS 22208   // 88832 bytes

static __device__ __forceinline__ float tanh_fast(float x) {
    float y; asm("tanh.approx.f32 %0, %1;" : "=f"(y) : "f"(x)); return y;
}
static __device__ __forceinline__ u32 f2h2(float a, float b) {
    __half2 h = __floats2half2_rn(a, b); return *(u32*)&h;
}
static __device__ __forceinline__ void cp16(void* dst, const void* src) {
    u32 sa = (u32)__cvta_generic_to_shared(dst);
    asm volatile("cp.async.cg.shared.global [%0], [%1], 16;" :: "r"(sa), "l"(src));
}
static __device__ __forceinline__ void mma16816(float* c, u32 a0, u32 a1, u32 a2, u32 a3,
                                                u32 b0, u32 b1) {
    asm volatile("mma.sync.aligned.m16n8k16.row.col.f32.f16.f16.f32 "
        "{%0,%1,%2,%3},{%4,%5,%6,%7},{%8,%9},{%0,%1,%2,%3};"
        : "+f"(c[0]), "+f"(c[1]), "+f"(c[2]), "+f"(c[3])
        : "r"(a0), "r"(a1), "r"(a2), "r"(a3), "r"(b0), "r"(b1));
}
static __device__ __forceinline__ void ldsm4(u32 addr, u32& a0, u32& a1, u32& a2, u32& a3) {
    asm volatile("ldmatrix.sync.aligned.m8n8.x4.shared.b16 {%0,%1,%2,%3},[%4];"
        : "=r"(a0), "=r"(a1), "=r"(a2), "=r"(a3) : "r"(addr));
}
static __device__ __forceinline__ void ldsm4t(u32 addr, u32& a0, u32& a1, u32& a2, u32& a3) {
    asm volatile("ldmatrix.sync.aligned.m8n8.x4.trans.shared.b16 {%0,%1,%2,%3},[%4];"
        : "=r"(a0), "=r"(a1), "=r"(a2), "=r"(a3) : "r"(addr));
}

__global__ __launch_bounds__(512, 2) void attn_v13(
    const float* __restrict__ emb, const float* __restrict__ Wn,
    const float* __restrict__ Wf, const float* __restrict__ Ws,
    const float* __restrict__ Wo, const int* __restrict__ fidx,
    const int* __restrict__ lidx, const int* __restrict__ mask,
    float* __restrict__ out)
{
    extern __shared__ float sm[];
    __half* smh = (__half*)sm;
    const int b = blockIdx.x, t = threadIdx.x;
    const int lane = t & 31, warp = t >> 5;
    const float* embB = emb + (size_t)b * NN * DD;
    const int* mkB = mask + (size_t)b * NN;
    __half2* e16B = g_e16 + (size_t)b * (NN * 64);
    const u32 sbase = (u32)__cvta_generic_to_shared(sm);

    // chunk ch (0..7): rows ch*128..+128, all 128 dims, 272B padded rows
    auto stage = [&](int ch) {
        char* dstb = (char*)sm + (ch & 1) * 34816;
        const uint4* src = (const uint4*)e16B;
        #pragma unroll
        for (int k = 0; k < 4; k++) {
            int i = (k << 9) + t;          // 0..2047
            int row = i >> 4, seg = i & 15;
            int gr = ch * 128 + row; if (gr > NN - 1) gr = NN - 1;
            cp16(dstb + row * 272 + seg * 16, src + (size_t)gr * 16 + seg);
        }
        asm volatile("cp.async.commit_group;" ::: "memory");
    };

    // ---- Phase 0: mean partials (O_P) + fp16 conversion, MLP=8 ----
    {
        int c = t & 31, g = t >> 5;
        const float4* E4 = (const float4*)embB + c;
        uint2* O = (uint2*)e16B + c;
        float sx = 0, sy = 0, sz = 0, sw = 0;
        int k = 0;
        for (; k < 56; k += 8) {
            float4 v[8];
            #pragma unroll
            for (int j = 0; j < 8; j++) v[j] = E4[(size_t)(g + ((k + j) << 4)) * 32];
            #pragma unroll
            for (int j = 0; j < 8; j++) {
                uint2 h; h.x = f2h2(v[j].x, v[j].y); h.y = f2h2(v[j].z, v[j].w);
                O[(size_t)(g + ((k + j) << 4)) * 32] = h;
                sx += v[j].x; sy += v[j].y; sz += v[j].z; sw += v[j].w;
            }
        }
        for (; k < 63; k++) {
            int r = g + (k << 4);
            if (r < NN) {
                float4 v = E4[(size_t)r * 32];
                uint2 h; h.x = f2h2(v.x, v.y); h.y = f2h2(v.z, v.w);
                O[(size_t)r * 32] = h;
                sx += v.x; sy += v.y; sz += v.z; sw += v.w;
            }
        }
        *(float4*)(sm + O_P + g * 128 + c * 4) = make_float4(sx, sy, sz, sw);
    }
    if (t < 128)      sm[O_S2 + t] = embB[(size_t)fidx[b] * DD + t];
    else if (t < 256) sm[O_S3 + t - 128] = embB[(size_t)lidx[b] * DD + (t - 128)];
    __syncthreads();
    stage(0);   // P12 chunk 0 fills under mean/q/qt
    if (t < 128) {
        float m = 0.f;
        #pragma unroll
        for (int g = 0; g < 16; g++) m += sm[O_P + g * 128 + t];
        sm[O_S0 + t] = m * (1.0f / NN);
    }
    if (t < 8) { sm[O_MS + t] = -1e30f; sm[O_MS + 8 + t] = 0.f; }   // m, s init
    __syncthreads();
    // q = mean@Wf + [ef;el]@Ws
    if (t < 128) {
        float a0 = 0.f, a1 = 0.f;
        #pragma unroll 4
        for (int i = 0; i < DD; i += 2) {
            a0 += sm[O_S0 + i] * Wf[i * DD + t];
            a1 += sm[O_S0 + i + 1] * Wf[(i + 1) * DD + t];
        }
        #pragma unroll 4
        for (int i = 0; i < DD; i += 2) {
            a0 += sm[O_S2 + i] * Ws[i * DD + t];
            a1 += sm[O_S2 + i + 1] * Ws[(i + 1) * DD + t];
        }
        #pragma unroll 4
        for (int i = 0; i < DD; i += 2) {
            a0 += sm[O_S3 + i] * Ws[(DD + i) * DD + t];
            a1 += sm[O_S3 + i + 1] * Ws[(DD + i + 1) * DD + t];
        }
        sm[O_S1 + t] = a0 + a1;
    }
    __syncthreads();
    // qtT fp16 [head][136], scale folded
    if (t < 256) {
        int d = t >> 1, q4 = t & 1;
        #pragma unroll
        for (int kk = 0; kk < 4; kk++) {
            int h = q4 * 4 + kk;
            const float* w = Wn + d * 384 + h * 16;
            const float* qq = sm + O_S1 + h * 16;
            float acc = 0.f;
            #pragma unroll
            for (int j = 0; j < 16; j++) acc += w[j] * qq[j];
            smh[2 * O_QT + h * 136 + d] = __float2half(acc * 0.25f);
        }
    }
    __syncthreads();

    // ---- Fused P1+P2: flash-style compat + online softmax + ebar ----
    {
        const int m = warp & 7, kh = warp >> 3;
        const int g = lane >> 2, tc = lane & 3, hq = lane >> 2;
        // preload qt B-frags for this warp's k-half (4 ktiles)
        u32 bq0[4], bq1[4];
        #pragma unroll
        for (int j = 0; j < 4; j++) {
            int off = kh * 64 + j * 16 + 2 * tc;
            bq0[j] = *(const u32*)(smh + 2 * O_QT + hq * 136 + off);
            bq1[j] = *(const u32*)(smh + 2 * O_QT + hq * 136 + off + 8);
        }
        // ebar accumulator (persistent across chunks): warp m dims 16m..+16, k-half kh
        float eb[4] = {0.f, 0.f, 0.f, 0.f};
        const int srow = (lane & 7) + ((lane >> 4) & 1) * 8;
        const int doff = ((lane >> 3) & 1) * 16 + m * 32;
        const __half* atp = smh + 2 * O_AT + (lane >> 2) * 136 + 2 * (lane & 3);

        for (int ch = 0; ch < 8; ch++) {
            if (ch + 1 < 8) {
                stage(ch + 1);
                asm volatile("cp.async.wait_group 1;" ::: "memory");
            } else {
                asm volatile("cp.async.wait_group 0;" ::: "memory");
            }
            __syncthreads();   // bar1: tile ch ready; prev readers done
            const u32 bufb = sbase + (u32)((ch & 1) * 34816);

            // -- compat mma: tile rows m*16..+16, k-half kh --
            float cf[4] = {0.f, 0.f, 0.f, 0.f};
            #pragma unroll
            for (int j = 0; j < 4; j++) {
                u32 addr = bufb + (u32)((m * 16 + (lane & 15)) * 272 + (lane >> 4) * 16
                                        + kh * 128 + j * 32);
                u32 a0, a1, a2, a3;
                ldsm4(addr, a0, a1, a2, a3);
                mma16816(cf, a0, a1, a2, a3, bq0[j], bq1[j]);
            }
            // store compat partials f32: P[kh][head][row]
            {
                float* P = sm + O_P + kh * 1024;
                P[(2 * tc) * 128 + m * 16 + g]         = cf[0];
                P[(2 * tc + 1) * 128 + m * 16 + g]     = cf[1];
                P[(2 * tc) * 128 + m * 16 + g + 8]     = cf[2];
                P[(2 * tc + 1) * 128 + m * 16 + g + 8] = cf[3];
            }
            __syncthreads();   // bar2: compat partials visible

            // -- online softmax update: warp h (<8) handles head h --
            if (warp < 8) {
                const int h = warp;
                float m_old = sm[O_MS + h], s_old = sm[O_MS + 8 + h];
                float vals[4];
                #pragma unroll
                for (int k = 0; k < 4; k++) {
                    int r = k * 32 + lane;
                    float v = sm[O_P + h * 128 + r] + sm[O_P + 1024 + h * 128 + r];
                    int grow = ch * 128 + r;
                    if (grow >= NN || mkB[grow]) v = -1e30f;
                    vals[k] = v;
                }
                float cmax = fmaxf(fmaxf(vals[0], vals[1]), fmaxf(vals[2], vals[3]));
                #pragma unroll
                for (int o = 16; o > 0; o >>= 1)
                    cmax = fmaxf(cmax, __shfl_xor_sync(~0u, cmax, o));
                float m_new = fmaxf(m_old, cmax);
                float f = __expf(m_old - m_new);
                float csum = 0.f;
                __half* at = smh + 2 * O_AT + h * 136;
                #pragma unroll
                for (int k = 0; k < 4; k++) {
                    float e = __expf(vals[k] - m_new);
                    csum += e;
                    at[k * 32 + lane] = __float2half(e);
                }
                #pragma unroll
                for (int o = 16; o > 0; o >>= 1)
                    csum += __shfl_xor_sync(~0u, csum, o);
                if (lane == 0) {
                    sm[O_MS + h] = m_new;
                    sm[O_MS + 8 + h] = s_old * f + csum;
                    sm[O_MS + 16 + h] = f;
                }
            }
            __syncthreads();   // bar3: attn tile + f ready

            // -- ebar mma: rescale then accumulate this chunk --
            {
                float f0 = sm[O_MS + 16 + 2 * tc];
                float f1 = sm[O_MS + 16 + 2 * tc + 1];
                eb[0] *= f0; eb[1] *= f1; eb[2] *= f0; eb[3] *= f1;
                #pragma unroll
                for (int kt = 0; kt < 4; kt++) {
                    int rb = kh * 64 + kt * 16;
                    u32 b0 = *(const u32*)(atp + rb);
                    u32 b1 = *(const u32*)(atp + rb + 8);
                    u32 addr = bufb + (u32)((rb + srow) * 272 + doff);
                    u32 a0, a1, a2, a3;
                    ldsm4t(addr, a0, a1, a2, a3);
                    mma16816(eb, a0, a1, a2, a3, b0, b1);
                }
            }
            __syncthreads();   // bar4: tile + at consumed
        }
        stage(0);   // P3 chunk 0 fills under epilogue + matvecs
        // store ebar frags: P[kh*8+m][16][8]
        float* sp = sm + O_P;
        *(float2*)(sp + ((kh * 8 + m) * 16 + g) * 8 + 2 * tc)     = make_float2(eb[0], eb[1]);
        *(float2*)(sp + ((kh * 8 + m) * 16 + g + 8) * 8 + 2 * tc) = make_float2(eb[2], eb[3]);
    }
    if (t < 8) sm[O_MS + 24 + t] = 1.0f / sm[O_MS + 8 + t];   // inv
    __syncthreads();
    // assemble ebar[h][d] at O_LG (warp m covered dims [16m,16m+16))
    for (int i = t; i < 1024; i += 512) {
        int h = i >> 7, d = i & 127, m2 = d >> 4, g2 = d & 15;
        sm[O_LG + i] = (sm[O_P + (m2 * 16 + g2) * 8 + h]
                      + sm[O_P + ((8 + m2) * 16 + g2) * 8 + h]) * sm[O_MS + 24 + h];
    }
    __syncthreads();

    // ---- heads -> glimpse -> gtilde (+ gt16) ----
    if (t < 128) {
        int h = t >> 4;
        const float* ebp = sm + O_LG + h * 128;
        float a0 = 0.f, a1 = 0.f;
        #pragma unroll 4
        for (int d = 0; d < DD; d += 2) {
            a0 += ebp[d] * Wn[d * 384 + 128 + t];
            a1 += ebp[d + 1] * Wn[(d + 1) * 384 + 128 + t];
        }
        sm[O_S0 + t] = a0 + a1;
    }
    __syncthreads();
    if (t < 128) {
        float a0 = 0.f, a1 = 0.f;
        #pragma unroll 4
        for (int i = 0; i < DD; i += 2) {
            a0 += sm[O_S0 + i] * Wo[i * DD + t];
            a1 += sm[O_S0 + i + 1] * Wo[(i + 1) * DD + t];
        }
        sm[O_S1 + t] = a0 + a1;
    }
    __syncthreads();
    if (t < 128) {
        const float* w = Wn + t * 384 + 256;
        float a0 = 0.f, a1 = 0.f;
        #pragma unroll 4
        for (int j = 0; j < DD; j += 2) {
            a0 += w[j] * sm[O_S1 + j];
            a1 += w[j + 1] * sm[O_S1 + j + 1];
        }
        sm[O_S2 + t] = (a0 + a1) * 0.08838834764831845f;
    }
    __syncthreads();
    if (t < 64) ((u32*)(sm + O_GT16))[t] = f2h2(sm[O_S2 + 2 * t], sm[O_S2 + 2 * t + 1]);
    __syncthreads();

    // ---- Phase 3: logits via mma, 128x128 chunks, k split across warp pairs ----
    float* s_lg = sm + O_LG;
    float lmax = -1e30f;
    {
        const int m = warp & 7, kh = warp >> 3;
        const int g = lane >> 2;
        u32 bg0[4], bg1[4];
        #pragma unroll
        for (int j = 0; j < 4; j++) {
            if (lane < 4) {
                int off = kh * 64 + j * 16 + 2 * lane;
                bg0[j] = *(const u32*)(smh + 2 * O_GT16 + off);
                bg1[j] = *(const u32*)(smh + 2 * O_GT16 + off + 8);
            } else { bg0[j] = 0; bg1[j] = 0; }
        }
        for (int ch = 0; ch < 8; ch++) {
            if (ch + 1 < 8) {
                stage(ch + 1);
                asm volatile("cp.async.wait_group 1;" ::: "memory");
            } else {
                asm volatile("cp.async.wait_group 0;" ::: "memory");
            }
            __syncthreads();   // bar1
            const u32 bufb = sbase + (u32)((ch & 1) * 34816);
            float cf[4] = {0.f, 0.f, 0.f, 0.f};
            #pragma unroll
            for (int j = 0; j < 4; j++) {
                u32 addr = bufb + (u32)((m * 16 + (lane & 15)) * 272 + (lane >> 4) * 16
                                        + kh * 128 + j * 32);
                u32 a0, a1, a2, a3;
                ldsm4(addr, a0, a1, a2, a3);
                mma16816(cf, a0, a1, a2, a3, bg0[j], bg1[j]);
            }
            if ((lane & 3) == 0) {   // col 0 lanes
                sm[O_P + kh * 128 + m * 16 + g]     = cf[0];
                sm[O_P + kh * 128 + m * 16 + g + 8] = cf[2];
            }
            __syncthreads();   // bar2: partials visible
            if (t < 128) {
                int grow = ch * 128 + t;
                if (grow < NN) {
                    float v = tanh_fast(sm[O_P + t] + sm[O_P + 128 + t]) * 10.0f;
                    if (mkB[grow]) v = NEGV;
                    s_lg[grow] = v;
                    lmax = fmaxf(lmax, v);
                }
            }
            // next iteration's bar1 separates these reads from next partial stores
        }
    }
    __syncthreads();
    // ---- log-softmax over 1000 ----
    #pragma unroll
    for (int o = 16; o > 0; o >>= 1) lmax = fmaxf(lmax, __shfl_xor_sync(~0u, lmax, o));
    if (lane == 0) sm[O_RED + warp] = lmax;
    __syncthreads();
    float bmax = sm[O_RED + 0];
    #pragma unroll
    for (int w = 1; w < 16; w++) bmax = fmaxf(bmax, sm[O_RED + w]);
    float ls = 0.f;
    for (int n = t; n < NN; n += 512) ls += __expf(s_lg[n] - bmax);
    #pragma unroll
    for (int o = 16; o > 0; o >>= 1) ls += __shfl_xor_sync(~0u, ls, o);
    if (lane == 0) sm[O_RED + 16 + warp] = ls;
    __syncthreads();
    float tot = sm[O_RED + 16];
    #pragma unroll
    for (int w = 1; w < 16; w++) tot += sm[O_RED + 16 + w];
    float logZ = bmax + logf(tot);
    float* outB = out + (size_t)b * NN;
    for (int n = t; n < NN; n += 512) outB[n] = s_lg[n] - logZ;
}

extern "C" void kernel_launch(void* const* d_in, const int* in_sizes, int n_in,
                              void* d_out, int out_size) {
    const float* emb = (const float*)d_in[0];
    const float* Wn  = (const float*)d_in[1];
    const float* Wf  = (const float*)d_in[2];
    const float* Ws  = (const float*)d_in[3];
    const float* Wo  = (const float*)d_in[4];
    const int* fidx  = (const int*)d_in[5];
    const int* lidx  = (const int*)d_in[6];
    const int* mask  = (const int*)d_in[7];
    float* out = (float*)d_out;
    cudaFuncSetAttribute(attn_v13, cudaFuncAttributeMaxDynamicSharedMemorySize, SM_WORDS * 4);
    attn_v13<<<256, 512, SM_WORDS * 4>>>(emb, Wn, Wf, Ws, Wo, fidx, lidx, mask, out);
}

// round 17
// speedup vs baseline: 1.1869x; 1.0003x over previous
#include <cuda_runtime.h>
#include <cuda_fp16.h>

#define NN 1000
#define DD 128
#define NEGV (-1e9f)
typedef unsigned long long u64;
typedef unsigned int u32;

// fp16 copy of embeddings [b][row][128 halves], written by phase 0
__device__ __align__(16) __half2 g_e16[(size_t)256 * NN * 64];

// ---- smem float offsets ----
#define O_A     0        // 17408: four 64-row x 272B buffers (4352 floats each)
#define O_AT    17408    // 576: attn tiles fp16 [2 groups][8][72]
#define O_P     17984    // 2048: mean partials / compat partials / eb frags / P3 partials
#define O_LG    20032    // 1024: ebar[h][d] then s_lg[1000]
#define O_QT    21056    // 544: qtT fp16 [8][136]
#define O_GT16  21600    // 64: gt fp16 [128]
#define O_S0    21664    // mean / heads
#define O_S1    21792    // q / gl
#define O_S2    21920    // ef / gt
#define O_S3    22048    // el
#define O_MS    22176    // 96: per-group m[8],s[8],f[8] @ gid*32; merged wX@64,wY@72
#define O_RED   22272    // 32
#define SM_WORDS 22304   // 89216 bytes

static __device__ __forceinline__ float tanh_fast(float x) {
    float y; asm("tanh.approx.f32 %0, %1;" : "=f"(y) : "f"(x)); return y;
}
static __device__ __forceinline__ u32 f2h2(float a, float b) {
    __half2 h = __floats2half2_rn(a, b); return *(u32*)&h;
}
static __device__ __forceinline__ void cp16(void* dst, const void* src) {
    u32 sa = (u32)__cvta_generic_to_shared(dst);
    asm volatile("cp.async.cg.shared.global [%0], [%1], 16;" :: "r"(sa), "l"(src));
}
static __device__ __forceinline__ void mma16816(float* c, u32 a0, u32 a1, u32 a2, u32 a3,
                                                u32 b0, u32 b1) {
    asm volatile("mma.sync.aligned.m16n8k16.row.col.f32.f16.f16.f32 "
        "{%0,%1,%2,%3},{%4,%5,%6,%7},{%8,%9},{%0,%1,%2,%3};"
        : "+f"(c[0]), "+f"(c[1]), "+f"(c[2]), "+f"(c[3])
        : "r"(a0), "r"(a1), "r"(a2), "r"(a3), "r"(b0), "r"(b1));
}
static __device__ __forceinline__ void ldsm4(u32 addr, u32& a0, u32& a1, u32& a2, u32& a3) {
    asm volatile("ldmatrix.sync.aligned.m8n8.x4.shared.b16 {%0,%1,%2,%3},[%4];"
        : "=r"(a0), "=r"(a1), "=r"(a2), "=r"(a3) : "r"(addr));
}
static __device__ __forceinline__ void ldsm4t(u32 addr, u32& a0, u32& a1, u32& a2, u32& a3) {
    asm volatile("ldmatrix.sync.aligned.m8n8.x4.trans.shared.b16 {%0,%1,%2,%3},[%4];"
        : "=r"(a0), "=r"(a1), "=r"(a2), "=r"(a3) : "r"(addr));
}

__global__ __launch_bounds__(512, 2) void attn_v14(
    const float* __restrict__ emb, const float* __restrict__ Wn,
    const float* __restrict__ Wf, const float* __restrict__ Ws,
    const float* __restrict__ Wo, const int* __restrict__ fidx,
    const int* __restrict__ lidx, const int* __restrict__ mask,
    float* __restrict__ out)
{
    extern __shared__ float sm[];
    __half* smh = (__half*)sm;
    const int b = blockIdx.x, t = threadIdx.x;
    const int lane = t & 31, warp = t >> 5;
    const int gid = t >> 8;          // group 0 (even chunks) / 1 (odd chunks)
    const int gw = warp & 7;         // group-local warp id
    const int lt = t & 255;
    const float* embB = emb + (size_t)b * NN * DD;
    const int* mkB = mask + (size_t)b * NN;
    __half2* e16B = g_e16 + (size_t)b * (NN * 64);
    const u32 sbase = (u32)__cvta_generic_to_shared(sm);

    // stage 64-row chunk (chunk in 0..15) into group's buffer slot
    auto stageG = [&](int chunk, int slot) {
        char* dstb = (char*)sm + (gid * 2 + slot) * 17408;
        const uint4* src = (const uint4*)e16B;
        #pragma unroll
        for (int k = 0; k < 4; k++) {
            int i = (k << 8) + lt;          // 0..1023
            int row = i >> 4, seg = i & 15;
            int gr = chunk * 64 + row; if (gr > NN - 1) gr = NN - 1;
            cp16(dstb + row * 272 + seg * 16, src + (size_t)gr * 16 + seg);
        }
        asm volatile("cp.async.commit_group;" ::: "memory");
    };
    auto gbar = [&]() {
        asm volatile("bar.sync %0, 256;" :: "r"(gid + 1) : "memory");
    };

    // ---- Phase 0: mean partials (O_P) + fp16 conversion, MLP=8 ----
    {
        int c = t & 31, g = t >> 5;
        const float4* E4 = (const float4*)embB + c;
        uint2* O = (uint2*)e16B + c;
        float sx = 0, sy = 0, sz = 0, sw = 0;
        int k = 0;
        for (; k < 56; k += 8) {
            float4 v[8];
            #pragma unroll
            for (int j = 0; j < 8; j++) v[j] = E4[(size_t)(g + ((k + j) << 4)) * 32];
            #pragma unroll
            for (int j = 0; j < 8; j++) {
                uint2 h; h.x = f2h2(v[j].x, v[j].y); h.y = f2h2(v[j].z, v[j].w);
                O[(size_t)(g + ((k + j) << 4)) * 32] = h;
                sx += v[j].x; sy += v[j].y; sz += v[j].z; sw += v[j].w;
            }
        }
        for (; k < 63; k++) {
            int r = g + (k << 4);
            if (r < NN) {
                float4 v = E4[(size_t)r * 32];
                uint2 h; h.x = f2h2(v.x, v.y); h.y = f2h2(v.z, v.w);
                O[(size_t)r * 32] = h;
                sx += v.x; sy += v.y; sz += v.z; sw += v.w;
            }
        }
        *(float4*)(sm + O_P + g * 128 + c * 4) = make_float4(sx, sy, sz, sw);
    }
    if (t < 128)      sm[O_S2 + t] = embB[(size_t)fidx[b] * DD + t];
    else if (t < 256) sm[O_S3 + t - 128] = embB[(size_t)lidx[b] * DD + (t - 128)];
    __syncthreads();
    stageG(gid, 0);   // each group's chunk 0 fills under mean/q/qt
    if (t < 128) {
        float m = 0.f;
        #pragma unroll
        for (int g = 0; g < 16; g++) m += sm[O_P + g * 128 + t];
        sm[O_S0 + t] = m * (1.0f / NN);
    }
    if (t < 16) {   // per-group softmax state init
        int g2 = t >> 3, h = t & 7;
        sm[O_MS + g2 * 32 + h] = -1e30f;
        sm[O_MS + g2 * 32 + 8 + h] = 0.f;
    }
    __syncthreads();
    // q = mean@Wf + [ef;el]@Ws
    if (t < 128) {
        float a0 = 0.f, a1 = 0.f;
        #pragma unroll 4
        for (int i = 0; i < DD; i += 2) {
            a0 += sm[O_S0 + i] * Wf[i * DD + t];
            a1 += sm[O_S0 + i + 1] * Wf[(i + 1) * DD + t];
        }
        #pragma unroll 4
        for (int i = 0; i < DD; i += 2) {
            a0 += sm[O_S2 + i] * Ws[i * DD + t];
            a1 += sm[O_S2 + i + 1] * Ws[(i + 1) * DD + t];
        }
        #pragma unroll 4
        for (int i = 0; i < DD; i += 2) {
            a0 += sm[O_S3 + i] * Ws[(DD + i) * DD + t];
            a1 += sm[O_S3 + i + 1] * Ws[(DD + i + 1) * DD + t];
        }
        sm[O_S1 + t] = a0 + a1;
    }
    __syncthreads();
    // qtT fp16 [head][136], scale folded
    if (t < 256) {
        int d = t >> 1, q4 = t & 1;
        #pragma unroll
        for (int kk = 0; kk < 4; kk++) {
            int h = q4 * 4 + kk;
            const float* w = Wn + d * 384 + h * 16;
            const float* qq = sm + O_S1 + h * 16;
            float acc = 0.f;
            #pragma unroll
            for (int j = 0; j < 16; j++) acc += w[j] * qq[j];
            smh[2 * O_QT + h * 136 + d] = __float2half(acc * 0.25f);
        }
    }
    __syncthreads();   // groups diverge after this

    // ---- Fused P1+P2 per group: compat + online softmax + ebar ----
    {
        const int m = gw & 3, kh = gw >> 2;
        const int g = lane >> 2, tc = lane & 3, hq = lane >> 2;
        u32 bq0[4], bq1[4];
        #pragma unroll
        for (int j = 0; j < 4; j++) {
            int off = kh * 64 + j * 16 + 2 * tc;
            bq0[j] = *(const u32*)(smh + 2 * O_QT + hq * 136 + off);
            bq1[j] = *(const u32*)(smh + 2 * O_QT + hq * 136 + off + 8);
        }
        float eb[4] = {0.f, 0.f, 0.f, 0.f};
        const int srow = (lane & 7) + ((lane >> 4) & 1) * 8;
        const int doff = ((lane >> 3) & 1) * 16 + gw * 32;   // warp gw: dims [16gw,16gw+16)
        const __half* atp = smh + 2 * O_AT + gid * 576 + (lane >> 2) * 72 + 2 * (lane & 3);
        float* Pg = sm + O_P + gid * 1024;
        float* MSg = sm + O_MS + gid * 32;

        for (int it = 0; it < 8; it++) {
            int chunk = 2 * it + gid;
            gbar();   // prev compute done; buffer slot (it+1)&1 free
            if (it + 1 < 8) {
                stageG(chunk + 2, (it + 1) & 1);
                asm volatile("cp.async.wait_group 1;" ::: "memory");
            } else {
                asm volatile("cp.async.wait_group 0;" ::: "memory");
            }
            gbar();   // tile ready for whole group
            const u32 bufb = sbase + (u32)((gid * 2 + (it & 1)) * 17408);

            // compat: warp (m,kh): rows m*16..+16, dims kh*64..+64
            float cf[4] = {0.f, 0.f, 0.f, 0.f};
            #pragma unroll
            for (int j = 0; j < 4; j++) {
                u32 addr = bufb + (u32)((m * 16 + (lane & 15)) * 272 + (lane >> 4) * 16
                                        + kh * 128 + j * 32);
                u32 a0, a1, a2, a3;
                ldsm4(addr, a0, a1, a2, a3);
                mma16816(cf, a0, a1, a2, a3, bq0[j], bq1[j]);
            }
            Pg[kh * 512 + (2 * tc) * 64 + m * 16 + g]         = cf[0];
            Pg[kh * 512 + (2 * tc + 1) * 64 + m * 16 + g]     = cf[1];
            Pg[kh * 512 + (2 * tc) * 64 + m * 16 + g + 8]     = cf[2];
            Pg[kh * 512 + (2 * tc + 1) * 64 + m * 16 + g + 8] = cf[3];
            gbar();   // partials visible

            // online softmax: warp gw handles head gw over 64 rows
            {
                float m_old = MSg[gw], s_old = MSg[8 + gw];
                float v0, v1;
                {
                    int r = lane;
                    float v = Pg[gw * 64 + r] + Pg[512 + gw * 64 + r];
                    int grow = chunk * 64 + r;
                    if (grow >= NN || mkB[grow]) v = -1e30f;
                    v0 = v;
                }
                {
                    int r = 32 + lane;
                    float v = Pg[gw * 64 + r] + Pg[512 + gw * 64 + r];
                    int grow = chunk * 64 + r;
                    if (grow >= NN || mkB[grow]) v = -1e30f;
                    v1 = v;
                }
                float cmax = fmaxf(v0, v1);
                #pragma unroll
                for (int o = 16; o > 0; o >>= 1)
                    cmax = fmaxf(cmax, __shfl_xor_sync(~0u, cmax, o));
                float m_new = fmaxf(m_old, cmax);
                float f = __expf(m_old - m_new);
                float e0 = (v0 <= -1e29f) ? 0.f : __expf(v0 - m_new);
                float e1 = (v1 <= -1e29f) ? 0.f : __expf(v1 - m_new);
                __half* at = smh + 2 * O_AT + gid * 576 + gw * 72;
                at[lane] = __float2half(e0);
                at[32 + lane] = __float2half(e1);
                float csum = e0 + e1;
                #pragma unroll
                for (int o = 16; o > 0; o >>= 1)
                    csum += __shfl_xor_sync(~0u, csum, o);
                if (lane == 0) {
                    MSg[gw] = m_new;
                    MSg[8 + gw] = s_old * f + csum;
                    MSg[16 + gw] = f;
                }
            }
            gbar();   // attn tile + f ready

            // ebar: rescale then accumulate (full k=64, no kh split)
            {
                float f0 = MSg[16 + 2 * tc];
                float f1 = MSg[16 + 2 * tc + 1];
                eb[0] *= f0; eb[1] *= f1; eb[2] *= f0; eb[3] *= f1;
                #pragma unroll
                for (int kt = 0; kt < 4; kt++) {
                    int rb = kt * 16;
                    u32 b0 = *(const u32*)(atp + rb);
                    u32 b1 = *(const u32*)(atp + rb + 8);
                    u32 addr = bufb + (u32)((rb + srow) * 272 + doff);
                    u32 a0, a1, a2, a3;
                    ldsm4t(addr, a0, a1, a2, a3);
                    mma16816(eb, a0, a1, a2, a3, b0, b1);
                }
            }
        }
        gbar();   // last softmax partial reads done before eb overwrites Pg
        // store eb frags: Pg[(d)*8 + h] for this group's dims/heads
        Pg[(gw * 16 + g) * 8 + 2 * tc]         = eb[0];
        Pg[(gw * 16 + g) * 8 + 2 * tc + 1]     = eb[1];
        Pg[(gw * 16 + g + 8) * 8 + 2 * tc]     = eb[2];
        Pg[(gw * 16 + g + 8) * 8 + 2 * tc + 1] = eb[3];
        stageG(gid, 0);   // P3 chunk 0 fills under merge + matvecs
    }
    __syncthreads();

    // ---- merge group softmax states + assemble ebar[h][d] ----
    if (t < 8) {
        float mX = sm[O_MS + t],      sX = sm[O_MS + 8 + t];
        float mY = sm[O_MS + 32 + t], sY = sm[O_MS + 40 + t];
        float M = fmaxf(mX, mY);
        float eX = (mX <= -1e29f) ? 0.f : __expf(mX - M);
        float eY = (mY <= -1e29f) ? 0.f : __expf(mY - M);
        float S = sX * eX + sY * eY;
        sm[O_MS + 64 + t] = eX / S;
        sm[O_MS + 72 + t] = eY / S;
    }
    __syncthreads();
    for (int i = t; i < 1024; i += 512) {
        int d = i >> 3, h = i & 7;
        sm[O_LG + h * 128 + d] = sm[O_P + i] * sm[O_MS + 64 + h]
                               + sm[O_P + 1024 + i] * sm[O_MS + 72 + h];
    }
    __syncthreads();

    // ---- heads -> glimpse -> gtilde (+ gt16) ----
    if (t < 128) {
        int h = t >> 4;
        const float* ebp = sm + O_LG + h * 128;
        float a0 = 0.f, a1 = 0.f;
        #pragma unroll 4
        for (int d = 0; d < DD; d += 2) {
            a0 += ebp[d] * Wn[d * 384 + 128 + t];
            a1 += ebp[d + 1] * Wn[(d + 1) * 384 + 128 + t];
        }
        sm[O_S0 + t] = a0 + a1;
    }
    __syncthreads();
    if (t < 128) {
        float a0 = 0.f, a1 = 0.f;
        #pragma unroll 4
        for (int i = 0; i < DD; i += 2) {
            a0 += sm[O_S0 + i] * Wo[i * DD + t];
            a1 += sm[O_S0 + i + 1] * Wo[(i + 1) * DD + t];
        }
        sm[O_S1 + t] = a0 + a1;
    }
    __syncthreads();
    if (t < 128) {
        const float* w = Wn + t * 384 + 256;
        float a0 = 0.f, a1 = 0.f;
        #pragma unroll 4
        for (int j = 0; j < DD; j += 2) {
            a0 += w[j] * sm[O_S1 + j];
            a1 += w[j + 1] * sm[O_S1 + j + 1];
        }
        sm[O_S2 + t] = (a0 + a1) * 0.08838834764831845f;
    }
    __syncthreads();
    if (t < 64) ((u32*)(sm + O_GT16))[t] = f2h2(sm[O_S2 + 2 * t], sm[O_S2 + 2 * t + 1]);
    __syncthreads();

    // ---- Phase 3 per group: logits via mma (gt in B col 0) ----
    float* s_lg = sm + O_LG;
    float lmax = -1e30f;
    {
        const int m = gw & 3, kh = gw >> 2, g = lane >> 2;
        u32 bg0[4], bg1[4];
        #pragma unroll
        for (int j = 0; j < 4; j++) {
            if (lane < 4) {
                int off = kh * 64 + j * 16 + 2 * lane;
                bg0[j] = *(const u32*)(smh + 2 * O_GT16 + off);
                bg1[j] = *(const u32*)(smh + 2 * O_GT16 + off + 8);
            } else { bg0[j] = 0; bg1[j] = 0; }
        }
        float* Pg3 = sm + O_P + gid * 128;
        for (int it = 0; it < 8; it++) {
            int chunk = 2 * it + gid;
            gbar();   // prev epilogue done; buffer free
            if (it + 1 < 8) {
                stageG(chunk + 2, (it + 1) & 1);
                asm volatile("cp.async.wait_group 1;" ::: "memory");
            } else {
                asm volatile("cp.async.wait_group 0;" ::: "memory");
            }
            gbar();   // tile ready
            const u32 bufb = sbase + (u32)((gid * 2 + (it & 1)) * 17408);
            float cf[4] = {0.f, 0.f, 0.f, 0.f};
            #pragma unroll
            for (int j = 0; j < 4; j++) {
                u32 addr = bufb + (u32)((m * 16 + (lane & 15)) * 272 + (lane >> 4) * 16
                                        + kh * 128 + j * 32);
                u32 a0, a1, a2, a3;
                ldsm4(addr, a0, a1, a2, a3);
                mma16816(cf, a0, a1, a2, a3, bg0[j], bg1[j]);
            }
            if ((lane & 3) == 0) {
                Pg3[kh * 64 + m * 16 + g]     = cf[0];
                Pg3[kh * 64 + m * 16 + g + 8] = cf[2];
            }
            gbar();   // partials visible
            if (lt < 64) {
                int grow = chunk * 64 + lt;
                if (grow < NN) {
                    float v = tanh_fast(Pg3[lt] + Pg3[64 + lt]) * 10.0f;
                    if (mkB[grow]) v = NEGV;
                    s_lg[grow] = v;
                    lmax = fmaxf(lmax, v);
                }
            }
        }
    }
    __syncthreads();
    // ---- log-softmax over 1000 ----
    #pragma unroll
    for (int o = 16; o > 0; o >>= 1) lmax = fmaxf(lmax, __shfl_xor_sync(~0u, lmax, o));
    if (lane == 0) sm[O_RED + warp] = lmax;
    __syncthreads();
    float bmax = sm[O_RED + 0];
    #pragma unroll
    for (int w = 1; w < 16; w++) bmax = fmaxf(bmax, sm[O_RED + w]);
    float ls = 0.f;
    for (int n = t; n < NN; n += 512) ls += __expf(s_lg[n] - bmax);
    #pragma unroll
    for (int o = 16; o > 0; o >>= 1) ls += __shfl_xor_sync(~0u, ls, o);
    if (lane == 0) sm[O_RED + 16 + warp] = ls;
    __syncthreads();
    float tot = sm[O_RED + 16];
    #pragma unroll
    for (int w = 1; w < 16; w++) tot += sm[O_RED + 16 + w];
    float logZ = bmax + logf(tot);
    float* outB = out + (size_t)b * NN;
    for (int n = t; n < NN; n += 512) outB[n] = s_lg[n] - logZ;
}

extern "C" void kernel_launch(void* const* d_in, const int* in_sizes, int n_in,
                              void* d_out, int out_size) {
    const float* emb = (const float*)d_in[0];
    const float* Wn  = (const float*)d_in[1];
    const float* Wf  = (const float*)d_in[2];
    const float* Ws  = (const float*)d_in[3];
    const float* Wo  = (const float*)d_in[4];
    const int* fidx  = (const int*)d_in[5];
    const int* lidx  = (const int*)d_in[6];
    const int* mask  = (const int*)d_in[7];
    float* out = (float*)d_out;
    cudaFuncSetAttribute(attn_v14, cudaFuncAttributeMaxDynamicSharedMemorySize, SM_WORDS * 4);
    attn_v14<<<256, 512, SM_WORDS * 4>>>(emb, Wn, Wf, Ws, Wo, fidx, lidx, mask, out);
}